// round 10
// baseline (speedup 1.0000x reference)
#include <cuda_runtime.h>

#define Bn 4
#define Cn 256
#define Nn 131072           // D*H*W
#define NVEC2 (Nn / 2)      // 65536 float2 per batch
#define Kk 256
#define GCAP 32768          // global candidate capacity per batch
#define CPB 64              // CTAs per batch (grid = 4*64 = 256)

// ---------------- device scratch (static globals; no allocation) ------------
__device__ float2   g_scores2[Bn * NVEC2];  // 2 MiB scores (fallback only)
__device__ unsigned g_hist[Bn * 256];       // MSB-byte histograms (self-reset)
__device__ int      g_cgt[Bn];              // topk fill counters (self-reset)
__device__ int      g_ccand[Bn];            // candidate counters (self-reset)
__device__ int      g_eq[Bn];               // tie counters (self-reset)
__device__ int      g_barA[Bn];             // score->select barrier (self-reset)
__device__ int      g_barB[Bn];             // stash->refine barrier (self-reset)
__device__ int      g_barC[Bn];             // classify->gather barrier (self-reset)
__device__ int      g_arr2[Bn];             // reset-gate counters (self-reset)
__device__ uint2    g_cand[Bn * GCAP];      // (key, idx) straddling-bin stash
__device__ int      g_topk[Bn * Kk];        // fully rewritten each run

// monotone float->uint key: larger float => larger key
__device__ __forceinline__ unsigned fkey(float f) {
    unsigned u = __float_as_uint(f);
    return (u & 0x80000000u) ? ~u : (u | 0x80000000u);
}

// Warp-parallel straddling-bin selection over 32*NPL bins (higher index =
// higher rank). Finds max bin i where count(bins > i) < kk <= count(bins >= i).
template<int NPL>
__device__ __forceinline__ void warp_select(const unsigned* __restrict__ h,
                                            int kk, unsigned* out_idx, int* out_kk) {
    const int lane = threadIdx.x & 31;
    unsigned loc[NPL];
    unsigned chunk = 0;
#pragma unroll
    for (int j = 0; j < NPL; j++) { loc[j] = h[lane * NPL + j]; chunk += loc[j]; }
    unsigned pref = chunk;                       // inclusive prefix low->high lane
#pragma unroll
    for (int o = 1; o < 32; o <<= 1) {
        unsigned v = __shfl_up_sync(0xffffffffu, pref, o);
        if (lane >= o) pref += v;
    }
    unsigned total = __shfl_sync(0xffffffffu, pref, 31);
    unsigned cum = total - pref;                 // entries in higher lanes
#pragma unroll
    for (int j = NPL - 1; j >= 0; j--) {
        unsigned nc = cum + loc[j];
        if (cum < (unsigned)kk && nc >= (unsigned)kk) {
            *out_idx = (unsigned)(lane * NPL + j);
            *out_kk  = kk - (int)cum;
        }
        cum = nc;
    }
}

__device__ __forceinline__ void spin_until(volatile int* p, int target) {
    unsigned ns = 8;
    while (*p < target) { __nanosleep(ns); if (ns < 256) ns <<= 1; }
}

// ================= one persistent kernel: score+select+gather ================
__global__ void __launch_bounds__(1024, 2) fused_kernel(
        const float2* __restrict__ F2, const float* __restrict__ Ff,
        const float*  __restrict__ w,  float* __restrict__ out) {
    const int blk = blockIdx.x;
    const int b   = blk >> 6;            // batch (64 CTAs each)
    const int g   = blk & 63;            // CTA within batch
    const int t   = threadIdx.x;

    __shared__ float sw[Cn];
    __shared__ unsigned hist[256];
    __shared__ unsigned s_selbin, s_idx2;
    __shared__ int s_kk;

    // ---------------- phase 1: score my 1024-float2 slice -------------------
    for (int i = t; i < Cn; i += 1024) sw[i] = w[i];
    if (t < 256) hist[t] = 0;
    __syncthreads();

    const int nv = g * 1024 + t;                 // [0, NVEC2)
    float ax = 0.f, ay = 0.f;
    {
        const float2* base = F2 + (size_t)b * Cn * NVEC2 + nv;
#pragma unroll 8
        for (int c = 0; c < Cn; c++) {
            float2 x = __ldcs(&base[(size_t)c * NVEC2]);
            float wc = sw[c];
            ax = fmaf(x.x, wc, ax);
            ay = fmaf(x.y, wc, ay);
        }
        g_scores2[b * NVEC2 + nv] = make_float2(ax, ay);  // fallback path only

        unsigned kb[2] = { fkey(ax) >> 24, fkey(ay) >> 24 };
        const int lane = t & 31;
#pragma unroll
        for (int j = 0; j < 2; j++) {
            unsigned mask = __match_any_sync(0xffffffffu, kb[j]);
            if (lane == (__ffs(mask) - 1))
                atomicAdd(&hist[kb[j]], (unsigned)__popc(mask));
        }
    }
    __syncthreads();
    if (t < 256 && hist[t]) atomicAdd(&g_hist[b * 256 + t], hist[t]);

    // ---------------- barrier A: my batch's 64 CTAs done scoring ------------
    __threadfence();
    __syncthreads();
    if (t == 0) {
        atomicAdd(&g_barA[b], 1);
        spin_until(&g_barA[b], CPB);
    }
    __syncthreads();
    __threadfence();

    // ---------------- phase 2: select (register-resident scores) ------------
    if (t < 256) hist[t] = g_hist[b * 256 + t];
    __syncthreads();
    if (t < 32) warp_select<8>(hist, Kk, &s_selbin, &s_kk);
    __syncthreads();
    const unsigned selbin = s_selbin;
    int kk = s_kk;

    // stash straddling-bin entries / direct-write sure winners (from regs)
    {
        const unsigned key0 = fkey(ax), key1 = fkey(ay);
        unsigned keys[2] = { key0, key1 };
#pragma unroll
        for (int j = 0; j < 2; j++) {
            unsigned bin = keys[j] >> 24;
            if (bin < selbin) continue;
            int n = nv * 2 + j;
            if (bin > selbin) {
                int p = atomicAdd(&g_cgt[b], 1);     // guaranteed < Kk
                g_topk[b * Kk + p] = n;
            } else {
                int p = atomicAdd(&g_ccand[b], 1);
                if (p < GCAP) g_cand[b * GCAP + p] = make_uint2(keys[j], (unsigned)n);
            }
        }
    }
    __threadfence();
    __syncthreads();
    if (t == 0) {
        atomicAdd(&g_barB[b], 1);
        spin_until(&g_barB[b], CPB);                 // barrier B (full batch)
    }
    __syncthreads();
    __threadfence();

    // ---------------- phase 3: redundant radix refine (every CTA) -----------
    const int cnt_raw = g_ccand[b];
    const int cnt = cnt_raw < GCAP ? cnt_raw : GCAP;
    const bool fb = (cnt_raw > GCAP);
    const uint2* cand = g_cand + b * GCAP;
    const float* sc = (const float*)(g_scores2 + (size_t)b * NVEC2);

    unsigned prefix = selbin << 24, pmask = 0xFF000000u;
    for (int level = 2; level >= 0; level--) {
        if (t < 256) hist[t] = 0;
        __syncthreads();
        const int sh = 8 * level;
        if (!fb) {
            for (int i = t; i < cnt; i += 1024) {
                unsigned key = __ldg(&cand[i].x);
                if ((key & pmask) == prefix)
                    atomicAdd(&hist[(key >> sh) & 255], 1u);
            }
        } else {
            for (int i = t; i < Nn; i += 1024) {
                unsigned key = fkey(sc[i]);
                if ((key & pmask) == prefix)
                    atomicAdd(&hist[(key >> sh) & 255], 1u);
            }
        }
        __syncthreads();
        if (t < 32) warp_select<8>(hist, kk, &s_idx2, &s_kk);
        __syncthreads();
        prefix |= s_idx2 << sh;
        pmask  |= 0xFFu << sh;
        kk = s_kk;
        __syncthreads();
    }
    const unsigned T = prefix;
    const int rem = kk;                              // ties at T still needed

    // ---------------- phase 4: classify my register scores ------------------
    {
        const unsigned key0 = fkey(ax), key1 = fkey(ay);
        unsigned keys[2] = { key0, key1 };
#pragma unroll
        for (int j = 0; j < 2; j++) {
            unsigned key = keys[j];
            if ((key >> 24) != selbin) continue;     // winners already written
            int n = nv * 2 + j;
            if (key > T) {
                int p = atomicAdd(&g_cgt[b], 1);
                g_topk[b * Kk + p] = n;
            } else if (key == T) {
                int e = atomicAdd(&g_eq[b], 1);
                if (e < rem) g_topk[b * Kk + (Kk - rem) + e] = n;
            }
        }
    }
    __threadfence();
    __syncthreads();
    if (t == 0) {
        atomicAdd(&g_barC[b], 1);
        spin_until(&g_barC[b], CPB);                 // barrier C (topk complete)
    }
    __syncthreads();
    __threadfence();

    // last CTA through C resets all per-batch state for the next graph replay
    if (t == 0 && atomicAdd(&g_arr2[b], 1) == CPB - 1) {
        for (int i = 0; i < 256; i++) g_hist[b * 256 + i] = 0;
        g_cgt[b] = 0; g_ccand[b] = 0; g_eq[b] = 0;
        g_barA[b] = 0; g_barB[b] = 0; g_barC[b] = 0; g_arr2[b] = 0;
        __threadfence();
    }

    // ---------------- phase 5: gather 4 channels for this CTA + mean --------
    const int c0 = g * 4;                // 64 CTAs x 4 channels = 256
    const int j  = t & 255;              // voxel slot
    const int cp = t >> 8;               // 0..3 channel selector
    const int idx = g_topk[b * Kk + j];
    float v = __ldg(Ff + ((size_t)(b * Cn + c0 + cp)) * Nn + idx);

#pragma unroll
    for (int o = 16; o; o >>= 1) v += __shfl_down_sync(0xffffffffu, v, o);

    __shared__ float red[4][8];
    const int wg = (t >> 5) & 7;         // warp index within 256-thread group
    if ((t & 31) == 0) red[cp][wg] = v;
    __syncthreads();
    if (t < 4) {
        float s = 0.f;
#pragma unroll
        for (int q = 0; q < 8; q++) s += red[t][q];
        out[b * Cn + c0 + t] = s * (1.0f / Kk);
    }
}

// ---------------- launcher: single persistent kernel -------------------------
extern "C" void kernel_launch(void* const* d_in, const int* in_sizes, int n_in,
                              void* d_out, int out_size) {
    const float2* F2 = (const float2*)d_in[0];
    const float*  Ff = (const float*)d_in[0];
    const float*  w  = (const float*)d_in[1];
    float*        out = (float*)d_out;

    fused_kernel<<<Bn * CPB, 1024>>>(F2, Ff, w, out);
}

// round 12
// speedup vs baseline: 1.0027x; 1.0027x over previous
#include <cuda_runtime.h>

#define Bn 4
#define Cn 256
#define Nn 131072           // D*H*W
#define NVEC2 (Nn / 2)      // 65536 float2 per batch
#define Kk 256
#define GCAP 32768          // global candidate capacity per batch
#define CPB 64              // CTAs per batch (grid = 4*64 = 256)
#define MCAP 2048           // shared filtered-match capacity

// ---------------- device scratch (static globals; no allocation) ------------
__device__ float2   g_scores2[Bn * NVEC2];  // 2 MiB scores (fallback only)
__device__ unsigned g_hist[Bn * 256];       // MSB-byte histograms (self-reset)
__device__ unsigned g_hist2[Bn * 256];      // bits[23:16] histograms (self-reset)
__device__ int      g_cgt[Bn];              // topk fill counters (self-reset)
__device__ int      g_ccand[Bn];            // candidate counters (self-reset)
__device__ int      g_eq[Bn];               // tie counters (self-reset)
__device__ int      g_barA[Bn];             // score->select barrier (self-reset)
__device__ int      g_barB[Bn];             // stash->refine barrier (self-reset)
__device__ int      g_barC[Bn];             // classify->gather barrier (self-reset)
__device__ int      g_arr2[Bn];             // reset-gate counters (self-reset)
__device__ uint2    g_cand[Bn * GCAP];      // (key, voxel idx) stash
__device__ int      g_topk[Bn * Kk];        // fully rewritten each run

// monotone float->uint key: larger float => larger key
__device__ __forceinline__ unsigned fkey(float f) {
    unsigned u = __float_as_uint(f);
    return (u & 0x80000000u) ? ~u : (u | 0x80000000u);
}

// Warp-parallel straddling-bin selection over 32*NPL bins (higher index =
// higher rank). Finds max bin i where count(bins > i) < kk <= count(bins >= i).
template<int NPL>
__device__ __forceinline__ void warp_select(const unsigned* __restrict__ h,
                                            int kk, unsigned* out_idx, int* out_kk) {
    const int lane = threadIdx.x & 31;
    unsigned loc[NPL];
    unsigned chunk = 0;
#pragma unroll
    for (int j = 0; j < NPL; j++) { loc[j] = h[lane * NPL + j]; chunk += loc[j]; }
    unsigned pref = chunk;                       // inclusive prefix low->high lane
#pragma unroll
    for (int o = 1; o < 32; o <<= 1) {
        unsigned v = __shfl_up_sync(0xffffffffu, pref, o);
        if (lane >= o) pref += v;
    }
    unsigned total = __shfl_sync(0xffffffffu, pref, 31);
    unsigned cum = total - pref;                 // entries in higher lanes
#pragma unroll
    for (int j = NPL - 1; j >= 0; j--) {
        unsigned nc = cum + loc[j];
        if (cum < (unsigned)kk && nc >= (unsigned)kk) {
            *out_idx = (unsigned)(lane * NPL + j);
            *out_kk  = kk - (int)cum;
        }
        cum = nc;
    }
}

__device__ __forceinline__ void spin_until(volatile int* p, int target) {
    unsigned ns = 8;
    while (*p < target) { __nanosleep(ns); if (ns < 64) ns <<= 1; }
}

// warp-aggregated slot allocation. ONLY legal from straight-line code where
// every lane of the warp participates (no divergent loop bounds!).
__device__ __forceinline__ int warp_alloc(int* ctr, bool pred) {
    unsigned mask = __ballot_sync(0xffffffffu, pred);
    if (!mask) return -1;
    const int lane = threadIdx.x & 31;
    int leader = __ffs(mask) - 1;
    int base = 0;
    if (lane == leader) base = atomicAdd(ctr, __popc(mask));
    base = __shfl_sync(0xffffffffu, base, leader);
    return pred ? base + __popc(mask & ((1u << lane) - 1)) : -1;
}

// ================= one persistent kernel: score+select+gather ================
__global__ void __launch_bounds__(1024, 2) fused_kernel(
        const float2* __restrict__ F2, const float* __restrict__ Ff,
        const float*  __restrict__ w,  float* __restrict__ out) {
    const int blk = blockIdx.x;
    const int b   = blk >> 6;            // batch (64 CTAs each)
    const int g   = blk & 63;            // CTA within batch
    const int t   = threadIdx.x;

    __shared__ float sw[Cn];
    __shared__ unsigned hist[256];
    __shared__ unsigned smatch[MCAP];
    __shared__ unsigned s_selbin, s_idx2;
    __shared__ int s_kk, s_m;

    // ---------------- phase 1: score my 1024-float2 slice -------------------
    for (int i = t; i < Cn; i += 1024) sw[i] = w[i];
    if (t < 256) hist[t] = 0;
    __syncthreads();

    const int nv = g * 1024 + t;                 // [0, NVEC2)
    float ax = 0.f, ay = 0.f;
    {
        const float2* base = F2 + (size_t)b * Cn * NVEC2 + nv;
#pragma unroll 16
        for (int c = 0; c < Cn; c++) {
            float2 x = __ldcs(&base[(size_t)c * NVEC2]);
            float wc = sw[c];
            ax = fmaf(x.x, wc, ax);
            ay = fmaf(x.y, wc, ay);
        }
        g_scores2[b * NVEC2 + nv] = make_float2(ax, ay);  // fallback path only

        unsigned kb[2] = { fkey(ax) >> 24, fkey(ay) >> 24 };
        const int lane = t & 31;
#pragma unroll
        for (int j = 0; j < 2; j++) {
            unsigned mask = __match_any_sync(0xffffffffu, kb[j]);
            if (lane == (__ffs(mask) - 1))
                atomicAdd(&hist[kb[j]], (unsigned)__popc(mask));
        }
    }
    __syncthreads();
    if (t < 256 && hist[t]) atomicAdd(&g_hist[b * 256 + t], hist[t]);

    // ---------------- barrier A: my batch's 64 CTAs done scoring ------------
    __threadfence();
    __syncthreads();
    if (t == 0) {
        atomicAdd(&g_barA[b], 1);
        spin_until(&g_barA[b], CPB);
    }
    __syncthreads();
    __threadfence();

    // ---------------- phase 2: selbin + stash (registers) + hist2 -----------
    if (t < 256) hist[t] = g_hist[b * 256 + t];
    __syncthreads();
    if (t < 32) warp_select<8>(hist, Kk, &s_selbin, &s_kk);
    __syncthreads();
    const unsigned selbin = s_selbin;
    int kk = s_kk;

    if (t < 256) hist[t] = 0;                    // reuse as hist2 accumulator
    __syncthreads();

    const unsigned key0 = fkey(ax), key1 = fkey(ay);
    {
        // straight-line: every thread executes both j iterations (warp_alloc OK)
        unsigned keys[2] = { key0, key1 };
#pragma unroll
        for (int j = 0; j < 2; j++) {
            unsigned key = keys[j];
            unsigned bin = key >> 24;
            int n = nv * 2 + j;
            bool win  = (bin > selbin);
            bool cnd  = (bin == selbin);
            int pw = warp_alloc(&g_cgt[b], win);
            if (win) g_topk[b * Kk + pw] = n;    // guaranteed < Kk
            int pc = warp_alloc(&g_ccand[b], cnd);
            if (cnd) {
                if (pc < GCAP) g_cand[b * GCAP + pc] = make_uint2(key, (unsigned)n);
                atomicAdd(&hist[(key >> 16) & 255], 1u);
            }
        }
    }
    __syncthreads();
    if (t < 256 && hist[t]) atomicAdd(&g_hist2[b * 256 + t], hist[t]);

    __threadfence();
    __syncthreads();
    if (t == 0) {
        atomicAdd(&g_barB[b], 1);
        spin_until(&g_barB[b], CPB);             // barrier B (full batch)
    }
    __syncthreads();
    __threadfence();

    // ---------------- phase 3: resolve threshold -----------------------------
    const int cnt_raw = g_ccand[b];
    const int cnt = cnt_raw < GCAP ? cnt_raw : GCAP;
    const bool fb = (cnt_raw > GCAP);
    const uint2* cand = g_cand + b * GCAP;
    unsigned T; int rem;

    if (!fb) {
        // bits[23:16] level was prepaid in phase 2: resolve it now
        if (t < 256) hist[t] = g_hist2[b * 256 + t];
        __syncthreads();
        if (t < 32) warp_select<8>(hist, kk, &s_idx2, &s_kk);
        if (t == 0) s_m = 0;
        __syncthreads();
        const unsigned prefix16 = (selbin << 8) | s_idx2;
        kk = s_kk;
        __syncthreads();

        // one scan: filter stash to 16-bit-prefix matches (expected ~11).
        // plain per-thread atomics: loop bound is divergent, no warp sync here.
        for (int i = t; i < cnt; i += 1024) {
            unsigned key = __ldg(&cand[i].x);
            if ((key >> 16) == prefix16) {
                int p = atomicAdd(&s_m, 1);
                if (p < MCAP) smatch[p] = key;
            }
        }
        __syncthreads();
        int mcnt = s_m;

        if (mcnt <= MCAP) {
            // two cheap 8-bit levels over the tiny match set
            unsigned pfx = prefix16 << 16;
#pragma unroll
            for (int level = 1; level >= 0; level--) {
                if (t < 256) hist[t] = 0;
                __syncthreads();
                const int sh = 8 * level;
                const unsigned pm = (level == 1) ? 0xFFFF0000u : 0xFFFFFF00u;
                for (int i = t; i < mcnt; i += 1024) {
                    unsigned key = smatch[i];
                    if ((key & pm) == pfx)
                        atomicAdd(&hist[(key >> sh) & 255], 1u);
                }
                __syncthreads();
                if (t < 32) warp_select<8>(hist, kk, &s_idx2, &s_kk);
                __syncthreads();
                pfx |= s_idx2 << sh;
                kk = s_kk;
                __syncthreads();
            }
            T = pfx; rem = kk;
        } else {
            // rare: match overflow -> classic 2-level radix over full stash
            unsigned pfx = prefix16 << 16, pm = 0xFFFF0000u;
            for (int level = 1; level >= 0; level--) {
                if (t < 256) hist[t] = 0;
                __syncthreads();
                const int sh = 8 * level;
                for (int i = t; i < cnt; i += 1024) {
                    unsigned key = __ldg(&cand[i].x);
                    if ((key & pm) == pfx)
                        atomicAdd(&hist[(key >> sh) & 255], 1u);
                }
                __syncthreads();
                if (t < 32) warp_select<8>(hist, kk, &s_idx2, &s_kk);
                __syncthreads();
                pfx |= s_idx2 << sh;
                pm  |= 0xFFu << sh;
                kk = s_kk;
                __syncthreads();
            }
            T = pfx; rem = kk;
        }
    } else {
        // stash overflow: 3 radix levels over the scores array (correct, slow)
        const float* sc = (const float*)(g_scores2 + (size_t)b * NVEC2);
        unsigned pfx = selbin << 24, pm = 0xFF000000u;
        for (int level = 2; level >= 0; level--) {
            if (t < 256) hist[t] = 0;
            __syncthreads();
            const int sh = 8 * level;
            for (int i = t; i < Nn; i += 1024) {
                unsigned key = fkey(sc[i]);
                if ((key & pm) == pfx)
                    atomicAdd(&hist[(key >> sh) & 255], 1u);
            }
            __syncthreads();
            if (t < 32) warp_select<8>(hist, kk, &s_idx2, &s_kk);
            __syncthreads();
            pfx |= s_idx2 << sh;
            pm  |= 0xFFu << sh;
            kk = s_kk;
            __syncthreads();
        }
        T = pfx; rem = kk;
    }

    // ---------------- phase 4: classify my register scores ------------------
    {
        unsigned keys[2] = { key0, key1 };
#pragma unroll
        for (int j = 0; j < 2; j++) {
            unsigned key = keys[j];
            if ((key >> 24) != selbin) continue; // winners already written
            int n = nv * 2 + j;
            if (key > T) {
                int p = atomicAdd(&g_cgt[b], 1);
                g_topk[b * Kk + p] = n;
            } else if (key == T) {
                int e = atomicAdd(&g_eq[b], 1);
                if (e < rem) g_topk[b * Kk + (Kk - rem) + e] = n;
            }
        }
    }
    __threadfence();
    __syncthreads();
    if (t == 0) {
        atomicAdd(&g_barC[b], 1);
        spin_until(&g_barC[b], CPB);             // barrier C (topk complete)
    }
    __syncthreads();
    __threadfence();

    // last CTA through C resets all per-batch state for the next graph replay
    if (t == 0 && atomicAdd(&g_arr2[b], 1) == CPB - 1) {
        for (int i = 0; i < 256; i++) {
            g_hist[b * 256 + i] = 0;
            g_hist2[b * 256 + i] = 0;
        }
        g_cgt[b] = 0; g_ccand[b] = 0; g_eq[b] = 0;
        g_barA[b] = 0; g_barB[b] = 0; g_barC[b] = 0; g_arr2[b] = 0;
        __threadfence();
    }

    // ---------------- phase 5: gather 4 channels for this CTA + mean --------
    const int c0 = g * 4;                // 64 CTAs x 4 channels = 256
    const int j  = t & 255;              // voxel slot
    const int cp = t >> 8;               // 0..3 channel selector
    const int idx = g_topk[b * Kk + j];
    float v = __ldg(Ff + ((size_t)(b * Cn + c0 + cp)) * Nn + idx);

#pragma unroll
    for (int o = 16; o; o >>= 1) v += __shfl_down_sync(0xffffffffu, v, o);

    __shared__ float red[4][8];
    const int wg = (t >> 5) & 7;         // warp index within 256-thread group
    if ((t & 31) == 0) red[cp][wg] = v;
    __syncthreads();
    if (t < 4) {
        float s = 0.f;
#pragma unroll
        for (int q = 0; q < 8; q++) s += red[t][q];
        out[b * Cn + c0 + t] = s * (1.0f / Kk);
    }
}

// ---------------- launcher: single persistent kernel -------------------------
extern "C" void kernel_launch(void* const* d_in, const int* in_sizes, int n_in,
                              void* d_out, int out_size) {
    const float2* F2 = (const float2*)d_in[0];
    const float*  Ff = (const float*)d_in[0];
    const float*  w  = (const float*)d_in[1];
    float*        out = (float*)d_out;

    fused_kernel<<<Bn * CPB, 1024>>>(F2, Ff, w, out);
}

// round 13
// speedup vs baseline: 1.0678x; 1.0650x over previous
#include <cuda_runtime.h>

#define Bn 4
#define Cn 256
#define Nn 131072           // D*H*W
#define NVEC2 (Nn / 2)      // 65536 float2 per batch
#define Kk 256
#define GCAP 32768          // global candidate capacity per batch
#define CPB 64              // CTAs per batch (grid = 4*64 = 256)
#define MCAP 2048           // shared filtered-match capacity
#define SKEY 0xC0000000u    // fkey(2.0f): static candidate threshold (bin edge)

// ---------------- device scratch (static globals; no allocation) ------------
__device__ float2   g_scores2[Bn * NVEC2];  // 2 MiB scores (fallback only)
__device__ unsigned g_hist[Bn * 256];       // candidate MSB hists (self-reset)
__device__ unsigned g_hist2[Bn * 256];      // bin-0xC0 bits[23:16] hists (self-reset)
__device__ int      g_cgt[Bn];              // topk fill counters (self-reset)
__device__ int      g_ccand[Bn];            // candidate counters (self-reset)
__device__ int      g_eq[Bn];               // tie counters (self-reset)
__device__ int      g_barA[Bn];             // score->resolve barrier (self-reset)
__device__ int      g_barC[Bn];             // classify->gather barrier (self-reset)
__device__ int      g_arr2[Bn];             // reset-gate counters (self-reset)
__device__ uint2    g_cand[Bn * GCAP];      // (key, voxel idx) stash
__device__ int      g_topk[Bn * Kk];        // fully rewritten each run

// monotone float->uint key: larger float => larger key
__device__ __forceinline__ unsigned fkey(float f) {
    unsigned u = __float_as_uint(f);
    return (u & 0x80000000u) ? ~u : (u | 0x80000000u);
}

// Warp-parallel straddling-bin selection over 32*NPL bins (higher index =
// higher rank). Finds max bin i where count(bins > i) < kk <= count(bins >= i).
template<int NPL>
__device__ __forceinline__ void warp_select(const unsigned* __restrict__ h,
                                            int kk, unsigned* out_idx, int* out_kk) {
    const int lane = threadIdx.x & 31;
    unsigned loc[NPL];
    unsigned chunk = 0;
#pragma unroll
    for (int j = 0; j < NPL; j++) { loc[j] = h[lane * NPL + j]; chunk += loc[j]; }
    unsigned pref = chunk;                       // inclusive prefix low->high lane
#pragma unroll
    for (int o = 1; o < 32; o <<= 1) {
        unsigned v = __shfl_up_sync(0xffffffffu, pref, o);
        if (lane >= o) pref += v;
    }
    unsigned total = __shfl_sync(0xffffffffu, pref, 31);
    unsigned cum = total - pref;                 // entries in higher lanes
#pragma unroll
    for (int j = NPL - 1; j >= 0; j--) {
        unsigned nc = cum + loc[j];
        if (cum < (unsigned)kk && nc >= (unsigned)kk) {
            *out_idx = (unsigned)(lane * NPL + j);
            *out_kk  = kk - (int)cum;
        }
        cum = nc;
    }
}

__device__ __forceinline__ void spin_until(volatile int* p, int target) {
    unsigned ns = 8;
    while (*p < target) { __nanosleep(ns); if (ns < 64) ns <<= 1; }
}

// warp-aggregated slot allocation. ONLY legal from straight-line code where
// every lane of the warp participates (no divergent loop bounds!).
__device__ __forceinline__ int warp_alloc(int* ctr, bool pred) {
    unsigned mask = __ballot_sync(0xffffffffu, pred);
    if (!mask) return -1;
    const int lane = threadIdx.x & 31;
    int leader = __ffs(mask) - 1;
    int base = 0;
    if (lane == leader) base = atomicAdd(ctr, __popc(mask));
    base = __shfl_sync(0xffffffffu, base, leader);
    return pred ? base + __popc(mask & ((1u << lane) - 1)) : -1;
}

// ================= one persistent kernel: score+select+gather ================
__global__ void __launch_bounds__(1024, 2) fused_kernel(
        const float2* __restrict__ F2, const float* __restrict__ Ff,
        const float*  __restrict__ w,  float* __restrict__ out) {
    const int blk = blockIdx.x;
    const int b   = blk >> 6;            // batch (64 CTAs each)
    const int g   = blk & 63;            // CTA within batch
    const int t   = threadIdx.x;

    __shared__ float sw[Cn];
    __shared__ unsigned hist[256];
    __shared__ unsigned hist2c[256];
    __shared__ unsigned smatch[MCAP];
    __shared__ unsigned s_selbin, s_idx2;
    __shared__ int s_kk, s_m;

    // ------- phase 1: score my slice + static-threshold stash + hists -------
    for (int i = t; i < Cn; i += 1024) sw[i] = w[i];
    if (t < 256) { hist[t] = 0; hist2c[t] = 0; }
    __syncthreads();

    const int nv = g * 1024 + t;                 // [0, NVEC2)
    float ax = 0.f, ay = 0.f;
    {
        const float2* base = F2 + (size_t)b * Cn * NVEC2 + nv;
#pragma unroll 16
        for (int c = 0; c < Cn; c++) {
            float2 x = __ldcs(&base[(size_t)c * NVEC2]);
            float wc = sw[c];
            ax = fmaf(x.x, wc, ax);
            ay = fmaf(x.y, wc, ay);
        }
        g_scores2[b * NVEC2 + nv] = make_float2(ax, ay);  // fallback path only
    }

    const unsigned key0 = fkey(ax), key1 = fkey(ay);
    {
        // straight-line: all lanes execute both iterations (warp_alloc legal)
        unsigned keys[2] = { key0, key1 };
#pragma unroll
        for (int j = 0; j < 2; j++) {
            unsigned key = keys[j];
            bool cnd = (key >= SKEY);            // candidate: score >= 2.0
            int pc = warp_alloc(&g_ccand[b], cnd);
            if (cnd) {
                int n = nv * 2 + j;
                if (pc < GCAP) g_cand[b * GCAP + pc] = make_uint2(key, (unsigned)n);
                atomicAdd(&hist[key >> 24], 1u);
                if ((key >> 24) == 0xC0u)
                    atomicAdd(&hist2c[(key >> 16) & 255], 1u);
            }
        }
    }
    __syncthreads();
    if (t < 256) {
        if (hist[t])   atomicAdd(&g_hist[b * 256 + t], hist[t]);
        if (hist2c[t]) atomicAdd(&g_hist2[b * 256 + t], hist2c[t]);
    }

    // ---------------- barrier A: batch's 64 CTAs scored + stashed -----------
    __threadfence();
    __syncthreads();
    if (t == 0) {
        atomicAdd(&g_barA[b], 1);
        spin_until(&g_barA[b], CPB);
    }
    __syncthreads();
    __threadfence();

    // ---------------- phase 2: resolve threshold T ---------------------------
    const int cnt_raw = g_ccand[b];
    const int cnt = cnt_raw < GCAP ? cnt_raw : GCAP;
    const bool ok = (cnt_raw >= Kk) && (cnt_raw <= GCAP);  // stash exact & complete
    const uint2* cand = g_cand + b * GCAP;
    unsigned T; int rem;
    int kk = Kk;

    if (ok) {
        // selbin from candidate-only MSB hist (exact for bins >= 0xC0)
        if (t < 256) hist[t] = g_hist[b * 256 + t];
        __syncthreads();
        if (t < 32) warp_select<8>(hist, kk, &s_selbin, &s_kk);
        __syncthreads();
        const unsigned selbin = s_selbin;
        kk = s_kk;
        __syncthreads();

        // bits[23:16] level: prepaid if selbin == 0xC0 (the expected case)
        if (selbin == 0xC0u) {
            if (t < 256) hist[t] = g_hist2[b * 256 + t];
        } else {
            if (t < 256) hist[t] = 0;
            __syncthreads();
            for (int i = t; i < cnt; i += 1024) {
                unsigned key = __ldg(&cand[i].x);
                if ((key >> 24) == selbin)
                    atomicAdd(&hist[(key >> 16) & 255], 1u);
            }
        }
        __syncthreads();
        if (t < 32) warp_select<8>(hist, kk, &s_idx2, &s_kk);
        if (t == 0) s_m = 0;
        __syncthreads();
        const unsigned prefix16 = (selbin << 8) | s_idx2;
        kk = s_kk;
        __syncthreads();

        // one scan: filter stash to 16-bit-prefix matches (expected ~11)
        for (int i = t; i < cnt; i += 1024) {
            unsigned key = __ldg(&cand[i].x);
            if ((key >> 16) == prefix16) {
                int p = atomicAdd(&s_m, 1);
                if (p < MCAP) smatch[p] = key;
            }
        }
        __syncthreads();
        int mcnt = s_m;

        if (mcnt <= MCAP) {
            unsigned pfx = prefix16 << 16;
#pragma unroll
            for (int level = 1; level >= 0; level--) {
                if (t < 256) hist[t] = 0;
                __syncthreads();
                const int sh = 8 * level;
                const unsigned pm = (level == 1) ? 0xFFFF0000u : 0xFFFFFF00u;
                for (int i = t; i < mcnt; i += 1024) {
                    unsigned key = smatch[i];
                    if ((key & pm) == pfx)
                        atomicAdd(&hist[(key >> sh) & 255], 1u);
                }
                __syncthreads();
                if (t < 32) warp_select<8>(hist, kk, &s_idx2, &s_kk);
                __syncthreads();
                pfx |= s_idx2 << sh;
                kk = s_kk;
                __syncthreads();
            }
            T = pfx; rem = kk;
        } else {
            // rare: match overflow -> 2-level radix over full stash
            unsigned pfx = prefix16 << 16, pm = 0xFFFF0000u;
            for (int level = 1; level >= 0; level--) {
                if (t < 256) hist[t] = 0;
                __syncthreads();
                const int sh = 8 * level;
                for (int i = t; i < cnt; i += 1024) {
                    unsigned key = __ldg(&cand[i].x);
                    if ((key & pm) == pfx)
                        atomicAdd(&hist[(key >> sh) & 255], 1u);
                }
                __syncthreads();
                if (t < 32) warp_select<8>(hist, kk, &s_idx2, &s_kk);
                __syncthreads();
                pfx |= s_idx2 << sh;
                pm  |= 0xFFu << sh;
                kk = s_kk;
                __syncthreads();
            }
            T = pfx; rem = kk;
        }
    } else {
        // fallback (stash incomplete or < K candidates): 4 full radix levels
        const float* sc = (const float*)(g_scores2 + (size_t)b * NVEC2);
        unsigned pfx = 0, pm = 0;
        for (int level = 3; level >= 0; level--) {
            if (t < 256) hist[t] = 0;
            __syncthreads();
            const int sh = 8 * level;
            for (int i = t; i < Nn; i += 1024) {
                unsigned key = fkey(sc[i]);
                if ((key & pm) == pfx)
                    atomicAdd(&hist[(key >> sh) & 255], 1u);
            }
            __syncthreads();
            if (t < 32) warp_select<8>(hist, kk, &s_idx2, &s_kk);
            __syncthreads();
            pfx |= s_idx2 << sh;
            pm  |= 0xFFu << sh;
            kk = s_kk;
            __syncthreads();
        }
        T = pfx; rem = kk;
    }

    // ---------------- phase 3: classify my register scores vs T -------------
    if (ok) {
        unsigned keys[2] = { key0, key1 };
#pragma unroll
        for (int j = 0; j < 2; j++) {
            unsigned key = keys[j];
            int n = nv * 2 + j;
            if (key > T) {
                int p = atomicAdd(&g_cgt[b], 1);   // exactly Kk - rem winners
                g_topk[b * Kk + p] = n;
            } else if (key == T) {
                int e = atomicAdd(&g_eq[b], 1);
                if (e < rem) g_topk[b * Kk + (Kk - rem) + e] = n;
            }
        }
    } else {
        // fallback classify (T may be below SKEY; registers still valid)
        unsigned keys[2] = { key0, key1 };
#pragma unroll
        for (int j = 0; j < 2; j++) {
            unsigned key = keys[j];
            int n = nv * 2 + j;
            if (key > T) {
                int p = atomicAdd(&g_cgt[b], 1);
                g_topk[b * Kk + p] = n;
            } else if (key == T) {
                int e = atomicAdd(&g_eq[b], 1);
                if (e < rem) g_topk[b * Kk + (Kk - rem) + e] = n;
            }
        }
    }
    __threadfence();
    __syncthreads();
    if (t == 0) {
        atomicAdd(&g_barC[b], 1);
        spin_until(&g_barC[b], CPB);             // barrier C (topk complete)
    }
    __syncthreads();
    __threadfence();

    // last CTA through C resets all per-batch state for the next graph replay
    if (t == 0 && atomicAdd(&g_arr2[b], 1) == CPB - 1) {
        for (int i = 0; i < 256; i++) {
            g_hist[b * 256 + i] = 0;
            g_hist2[b * 256 + i] = 0;
        }
        g_cgt[b] = 0; g_ccand[b] = 0; g_eq[b] = 0;
        g_barA[b] = 0; g_barC[b] = 0; g_arr2[b] = 0;
        __threadfence();
    }

    // ---------------- phase 4: gather 4 channels for this CTA + mean --------
    const int c0 = g * 4;                // 64 CTAs x 4 channels = 256
    const int j  = t & 255;              // voxel slot
    const int cp = t >> 8;               // 0..3 channel selector
    const int idx = g_topk[b * Kk + j];
    float v = __ldg(Ff + ((size_t)(b * Cn + c0 + cp)) * Nn + idx);

#pragma unroll
    for (int o = 16; o; o >>= 1) v += __shfl_down_sync(0xffffffffu, v, o);

    __shared__ float red[4][8];
    const int wg = (t >> 5) & 7;         // warp index within 256-thread group
    if ((t & 31) == 0) red[cp][wg] = v;
    __syncthreads();
    if (t < 4) {
        float s = 0.f;
#pragma unroll
        for (int q = 0; q < 8; q++) s += red[t][q];
        out[b * Cn + c0 + t] = s * (1.0f / Kk);
    }
}

// ---------------- launcher: single persistent kernel -------------------------
extern "C" void kernel_launch(void* const* d_in, const int* in_sizes, int n_in,
                              void* d_out, int out_size) {
    const float2* F2 = (const float2*)d_in[0];
    const float*  Ff = (const float*)d_in[0];
    const float*  w  = (const float*)d_in[1];
    float*        out = (float*)d_out;

    fused_kernel<<<Bn * CPB, 1024>>>(F2, Ff, w, out);
}

// round 14
// speedup vs baseline: 1.0682x; 1.0004x over previous
#include <cuda_runtime.h>

#define Bn 4
#define Cn 256
#define Nn 131072           // D*H*W
#define NVEC2 (Nn / 2)      // 65536 float2 per batch
#define Kk 256
#define GCAP 32768          // global candidate capacity per batch
#define CPB 64              // CTAs per batch (grid = 4*64 = 256)
#define MCAP 2048           // shared filtered-match capacity
#define SKEY 0xC0000000u    // fkey(2.0f): static candidate threshold (bin edge)

// ---------------- device scratch (static globals; no allocation) ------------
__device__ float2   g_scores2[Bn * NVEC2];  // 2 MiB scores (fallback only)
__device__ unsigned g_hist[Bn * 256];       // candidate MSB hists (self-reset)
__device__ unsigned g_hist2[Bn * 256];      // bin-0xC0 bits[23:16] hists (self-reset)
__device__ int      g_cgt[Bn];              // topk fill counters (self-reset)
__device__ int      g_ccand[Bn];            // candidate counters (self-reset)
__device__ int      g_eq[Bn];               // tie counters (self-reset)
__device__ int      g_barA[Bn];             // score->resolve barrier (self-reset)
__device__ int      g_barC[Bn];             // classify->gather barrier (self-reset)
__device__ int      g_arr2[Bn];             // reset-gate counters (self-reset)
__device__ uint2    g_cand[Bn * GCAP];      // (key, voxel idx) stash
__device__ int      g_topk[Bn * Kk];        // fully rewritten each run

// monotone float->uint key: larger float => larger key
__device__ __forceinline__ unsigned fkey(float f) {
    unsigned u = __float_as_uint(f);
    return (u & 0x80000000u) ? ~u : (u | 0x80000000u);
}

// Warp-parallel straddling-bin selection over 32*NPL bins (higher index =
// higher rank). Finds max bin i where count(bins > i) < kk <= count(bins >= i).
template<int NPL>
__device__ __forceinline__ void warp_select(const unsigned* __restrict__ h,
                                            int kk, unsigned* out_idx, int* out_kk) {
    const int lane = threadIdx.x & 31;
    unsigned loc[NPL];
    unsigned chunk = 0;
#pragma unroll
    for (int j = 0; j < NPL; j++) { loc[j] = h[lane * NPL + j]; chunk += loc[j]; }
    unsigned pref = chunk;                       // inclusive prefix low->high lane
#pragma unroll
    for (int o = 1; o < 32; o <<= 1) {
        unsigned v = __shfl_up_sync(0xffffffffu, pref, o);
        if (lane >= o) pref += v;
    }
    unsigned total = __shfl_sync(0xffffffffu, pref, 31);
    unsigned cum = total - pref;                 // entries in higher lanes
#pragma unroll
    for (int j = NPL - 1; j >= 0; j--) {
        unsigned nc = cum + loc[j];
        if (cum < (unsigned)kk && nc >= (unsigned)kk) {
            *out_idx = (unsigned)(lane * NPL + j);
            *out_kk  = kk - (int)cum;
        }
        cum = nc;
    }
}

__device__ __forceinline__ void spin_until(volatile int* p, int target) {
    unsigned ns = 8;
    while (*p < target) { __nanosleep(ns); if (ns < 64) ns <<= 1; }
}

// warp-aggregated slot allocation. ONLY legal from straight-line code where
// every lane of the warp participates (no divergent loop bounds!).
__device__ __forceinline__ int warp_alloc(int* ctr, bool pred) {
    unsigned mask = __ballot_sync(0xffffffffu, pred);
    if (!mask) return -1;
    const int lane = threadIdx.x & 31;
    int leader = __ffs(mask) - 1;
    int base = 0;
    if (lane == leader) base = atomicAdd(ctr, __popc(mask));
    base = __shfl_sync(0xffffffffu, base, leader);
    return pred ? base + __popc(mask & ((1u << lane) - 1)) : -1;
}

// ================= one persistent kernel: score+select+gather ================
__global__ void __launch_bounds__(1024, 2) fused_kernel(
        const float2* __restrict__ F2, const float* __restrict__ Ff,
        const float*  __restrict__ w,  float* __restrict__ out) {
    const int blk = blockIdx.x;
    const int b   = blk >> 6;            // batch (64 CTAs each)
    const int g   = blk & 63;            // CTA within batch
    const int t   = threadIdx.x;

    __shared__ float sw[Cn];
    __shared__ unsigned hist[256];
    __shared__ unsigned hist2c[256];
    __shared__ unsigned smatch[MCAP];
    __shared__ unsigned s_selbin, s_idx2;
    __shared__ int s_kk, s_m, s_reset;

    // ------- phase 1: score my slice + static-threshold stash + hists -------
    for (int i = t; i < Cn; i += 1024) sw[i] = w[i];
    if (t < 256) { hist[t] = 0; hist2c[t] = 0; }
    __syncthreads();

    const int nv = g * 1024 + t;                 // [0, NVEC2)
    float ax = 0.f, ay = 0.f;
    {
        const float2* base = F2 + (size_t)b * Cn * NVEC2 + nv;
        // two independent channel streams (c, c+128) for deeper MLP
        float ax1 = 0.f, ay1 = 0.f;
#pragma unroll 8
        for (int c = 0; c < Cn / 2; c++) {
            float2 x0 = __ldcs(&base[(size_t)c * NVEC2]);
            float2 x1 = __ldcs(&base[(size_t)(c + Cn / 2) * NVEC2]);
            float w0 = sw[c], w1 = sw[c + Cn / 2];
            ax  = fmaf(x0.x, w0, ax);
            ay  = fmaf(x0.y, w0, ay);
            ax1 = fmaf(x1.x, w1, ax1);
            ay1 = fmaf(x1.y, w1, ay1);
        }
        ax += ax1; ay += ay1;
        __stcs(&g_scores2[b * NVEC2 + nv], make_float2(ax, ay));  // fallback only
    }

    const unsigned key0 = fkey(ax), key1 = fkey(ay);
    {
        // straight-line: all lanes execute both iterations (warp_alloc legal)
        unsigned keys[2] = { key0, key1 };
#pragma unroll
        for (int j = 0; j < 2; j++) {
            unsigned key = keys[j];
            bool cnd = (key >= SKEY);            // candidate: score >= 2.0
            int pc = warp_alloc(&g_ccand[b], cnd);
            if (cnd) {
                int n = nv * 2 + j;
                if (pc < GCAP) g_cand[b * GCAP + pc] = make_uint2(key, (unsigned)n);
                atomicAdd(&hist[key >> 24], 1u);
                if ((key >> 24) == 0xC0u)
                    atomicAdd(&hist2c[(key >> 16) & 255], 1u);
            }
        }
    }
    __syncthreads();
    if (t < 256) {
        if (hist[t])   atomicAdd(&g_hist[b * 256 + t], hist[t]);
        if (hist2c[t]) atomicAdd(&g_hist2[b * 256 + t], hist2c[t]);
    }

    // ---------------- barrier A: batch's 64 CTAs scored + stashed -----------
    __threadfence();
    __syncthreads();
    if (t == 0) {
        atomicAdd(&g_barA[b], 1);
        spin_until(&g_barA[b], CPB);
    }
    __syncthreads();
    __threadfence();

    // ---------------- phase 2: resolve threshold T ---------------------------
    const int cnt_raw = g_ccand[b];
    const int cnt = cnt_raw < GCAP ? cnt_raw : GCAP;
    const bool ok = (cnt_raw >= Kk) && (cnt_raw <= GCAP);  // stash exact & complete
    const uint2* cand = g_cand + b * GCAP;
    unsigned T; int rem;
    int kk = Kk;

    if (ok) {
        // selbin from candidate-only MSB hist (exact for bins >= 0xC0)
        if (t < 256) hist[t] = g_hist[b * 256 + t];
        __syncthreads();
        if (t < 32) warp_select<8>(hist, kk, &s_selbin, &s_kk);
        __syncthreads();
        const unsigned selbin = s_selbin;
        kk = s_kk;
        __syncthreads();

        // bits[23:16] level: prepaid if selbin == 0xC0 (the expected case)
        if (selbin == 0xC0u) {
            if (t < 256) hist[t] = g_hist2[b * 256 + t];
        } else {
            if (t < 256) hist[t] = 0;
            __syncthreads();
            for (int i = t; i < cnt; i += 1024) {
                unsigned key = __ldg(&cand[i].x);
                if ((key >> 24) == selbin)
                    atomicAdd(&hist[(key >> 16) & 255], 1u);
            }
        }
        __syncthreads();
        if (t < 32) warp_select<8>(hist, kk, &s_idx2, &s_kk);
        if (t == 0) s_m = 0;
        __syncthreads();
        const unsigned prefix16 = (selbin << 8) | s_idx2;
        kk = s_kk;
        __syncthreads();

        // one scan: filter stash to 16-bit-prefix matches (expected ~11)
        for (int i = t; i < cnt; i += 1024) {
            unsigned key = __ldg(&cand[i].x);
            if ((key >> 16) == prefix16) {
                int p = atomicAdd(&s_m, 1);
                if (p < MCAP) smatch[p] = key;
            }
        }
        __syncthreads();
        int mcnt = s_m;

        if (mcnt <= MCAP) {
            unsigned pfx = prefix16 << 16;
#pragma unroll
            for (int level = 1; level >= 0; level--) {
                if (t < 256) hist[t] = 0;
                __syncthreads();
                const int sh = 8 * level;
                const unsigned pm = (level == 1) ? 0xFFFF0000u : 0xFFFFFF00u;
                for (int i = t; i < mcnt; i += 1024) {
                    unsigned key = smatch[i];
                    if ((key & pm) == pfx)
                        atomicAdd(&hist[(key >> sh) & 255], 1u);
                }
                __syncthreads();
                if (t < 32) warp_select<8>(hist, kk, &s_idx2, &s_kk);
                __syncthreads();
                pfx |= s_idx2 << sh;
                kk = s_kk;
                __syncthreads();
            }
            T = pfx; rem = kk;
        } else {
            // rare: match overflow -> 2-level radix over full stash
            unsigned pfx = prefix16 << 16, pm = 0xFFFF0000u;
            for (int level = 1; level >= 0; level--) {
                if (t < 256) hist[t] = 0;
                __syncthreads();
                const int sh = 8 * level;
                for (int i = t; i < cnt; i += 1024) {
                    unsigned key = __ldg(&cand[i].x);
                    if ((key & pm) == pfx)
                        atomicAdd(&hist[(key >> sh) & 255], 1u);
                }
                __syncthreads();
                if (t < 32) warp_select<8>(hist, kk, &s_idx2, &s_kk);
                __syncthreads();
                pfx |= s_idx2 << sh;
                pm  |= 0xFFu << sh;
                kk = s_kk;
                __syncthreads();
            }
            T = pfx; rem = kk;
        }
    } else {
        // fallback (stash incomplete or < K candidates): 4 full radix levels
        const float* sc = (const float*)(g_scores2 + (size_t)b * NVEC2);
        unsigned pfx = 0, pm = 0;
        for (int level = 3; level >= 0; level--) {
            if (t < 256) hist[t] = 0;
            __syncthreads();
            const int sh = 8 * level;
            for (int i = t; i < Nn; i += 1024) {
                unsigned key = fkey(sc[i]);
                if ((key & pm) == pfx)
                    atomicAdd(&hist[(key >> sh) & 255], 1u);
            }
            __syncthreads();
            if (t < 32) warp_select<8>(hist, kk, &s_idx2, &s_kk);
            __syncthreads();
            pfx |= s_idx2 << sh;
            pm  |= 0xFFu << sh;
            kk = s_kk;
            __syncthreads();
        }
        T = pfx; rem = kk;
    }

    // ---------------- phase 3: classify my register scores vs T -------------
    {
        unsigned keys[2] = { key0, key1 };
#pragma unroll
        for (int j = 0; j < 2; j++) {
            unsigned key = keys[j];
            int n = nv * 2 + j;
            if (key > T) {
                int p = atomicAdd(&g_cgt[b], 1);   // exactly Kk - rem winners
                g_topk[b * Kk + p] = n;
            } else if (key == T) {
                int e = atomicAdd(&g_eq[b], 1);
                if (e < rem) g_topk[b * Kk + (Kk - rem) + e] = n;
            }
        }
    }
    __threadfence();
    __syncthreads();
    if (t == 0) {
        atomicAdd(&g_barC[b], 1);
        spin_until(&g_barC[b], CPB);             // barrier C (topk complete)
    }
    __syncthreads();
    __threadfence();

    // elect reset CTA (work happens AFTER the output write, off critical path)
    if (t == 0) s_reset = (atomicAdd(&g_arr2[b], 1) == CPB - 1);
    __syncthreads();

    // ---------------- phase 4: gather 4 channels for this CTA + mean --------
    const int c0 = g * 4;                // 64 CTAs x 4 channels = 256
    const int j  = t & 255;              // voxel slot
    const int cp = t >> 8;               // 0..3 channel selector
    const int idx = g_topk[b * Kk + j];
    float v = __ldg(Ff + ((size_t)(b * Cn + c0 + cp)) * Nn + idx);

#pragma unroll
    for (int o = 16; o; o >>= 1) v += __shfl_down_sync(0xffffffffu, v, o);

    __shared__ float red[4][8];
    const int wg = (t >> 5) & 7;         // warp index within 256-thread group
    if ((t & 31) == 0) red[cp][wg] = v;
    __syncthreads();
    if (t < 4) {
        float s = 0.f;
#pragma unroll
        for (int q = 0; q < 8; q++) s += red[t][q];
        out[b * Cn + c0 + t] = s * (1.0f / Kk);
    }

    // ---------------- epilogue: parallel per-batch state reset --------------
    // Runs after the output write on the one elected CTA; ordered before the
    // next graph replay by kernel completion.
    if (s_reset) {
        if (t < 256) {
            g_hist[b * 256 + t] = 0;
            g_hist2[b * 256 + t] = 0;
        }
        if (t == 0) {
            g_cgt[b] = 0; g_ccand[b] = 0; g_eq[b] = 0;
            g_barA[b] = 0; g_barC[b] = 0; g_arr2[b] = 0;
            __threadfence();
        }
    }
}

// ---------------- launcher: single persistent kernel -------------------------
extern "C" void kernel_launch(void* const* d_in, const int* in_sizes, int n_in,
                              void* d_out, int out_size) {
    const float2* F2 = (const float2*)d_in[0];
    const float*  Ff = (const float*)d_in[0];
    const float*  w  = (const float*)d_in[1];
    float*        out = (float*)d_out;

    fused_kernel<<<Bn * CPB, 1024>>>(F2, Ff, w, out);
}